// round 3
// baseline (speedup 1.0000x reference)
#include <cuda_runtime.h>
#include <math.h>

#define B_   1024
#define T_   256
#define F_   128
#define H_   128
#define G4H  512
#define D_   256
#define A_   8

// ---------------- scratch (device globals; no allocation allowed) ----------
__device__ float g_xg[(size_t)B_ * T_ * G4H];   // 512 MB: input projections [B*T, 4H]
__device__ float g_x [B_ * H_];                 // final hidden state
__device__ float g_a1[B_ * D_];
__device__ float g_v1[B_ * D_];
__device__ float g_a2[B_ * D_];
__device__ float g_v2[B_ * D_];

// ---------------------------------------------------------------------------
// K1: xg = h @ Wx   ([B*T,128] @ [128,512])
// 64x64 block tile, BK=64 (two K phases), 256 threads, 4x4 microtile.
// ---------------------------------------------------------------------------
__global__ void __launch_bounds__(256) k_xg_gemm(const float* __restrict__ h,
                                                 const float* __restrict__ Wx) {
    __shared__ float As[64][64];   // As[k][m]
    __shared__ float Bs[64][64];   // Bs[k][n]

    const int tid = threadIdx.x;
    const int m0  = blockIdx.x * 64;
    const int n0  = blockIdx.y * 64;
    const int ty  = tid >> 4;      // 0..15
    const int tx  = tid & 15;      // 0..15

    float acc[4][4] = {};

    #pragma unroll
    for (int k0 = 0; k0 < F_; k0 += 64) {
        // load A tile (transpose into As[k][m])
        #pragma unroll
        for (int t = 0; t < 4; t++) {
            int linear = tid + 256 * t;          // 0..1023
            int m  = linear >> 4;                // 0..63
            int kq = (linear & 15) << 2;         // 0,4,...,60
            float4 v = *(const float4*)&h[(size_t)(m0 + m) * F_ + k0 + kq];
            As[kq + 0][m] = v.x;
            As[kq + 1][m] = v.y;
            As[kq + 2][m] = v.z;
            As[kq + 3][m] = v.w;
        }
        // load B tile
        #pragma unroll
        for (int t = 0; t < 4; t++) {
            int linear = tid + 256 * t;
            int kb = linear >> 4;                // 0..63
            int n4 = (linear & 15) << 2;         // 0..60
            *(float4*)&Bs[kb][n4] =
                *(const float4*)&Wx[(size_t)(k0 + kb) * G4H + n0 + n4];
        }
        __syncthreads();

        #pragma unroll 8
        for (int k = 0; k < 64; k++) {
            float4 a4 = *(const float4*)&As[k][ty << 2];
            float4 b4 = *(const float4*)&Bs[k][tx << 2];
            float av[4] = {a4.x, a4.y, a4.z, a4.w};
            float bv[4] = {b4.x, b4.y, b4.z, b4.w};
            #pragma unroll
            for (int i = 0; i < 4; i++)
                #pragma unroll
                for (int j = 0; j < 4; j++)
                    acc[i][j] += av[i] * bv[j];
        }
        __syncthreads();
    }

    #pragma unroll
    for (int i = 0; i < 4; i++) {
        float4 v = make_float4(acc[i][0], acc[i][1], acc[i][2], acc[i][3]);
        *(float4*)&g_xg[(size_t)(m0 + (ty << 2) + i) * G4H + n0 + (tx << 2)] = v;
    }
}

// ---------------------------------------------------------------------------
// K2: fused LSTM scan. Each CTA owns BM=8 batch rows for all T=256 steps.
// 256 threads; thread j computes z columns (2j, 2j+1) for all 8 rows.
// Wh streamed from L2 each step (Wh is 256KB, resident in L2).
// ---------------------------------------------------------------------------
#define BM 8

__global__ void __launch_bounds__(256) k_lstm(const float* __restrict__ Wh,
                                              const float* __restrict__ bh) {
    __shared__ float hs_s[128][BM];      // transposed: hs_s[k][r]
    __shared__ float c_s[BM][128];
    __shared__ float z_s[BM][G4H];

    const int tid = threadIdx.x;
    const int r0  = blockIdx.x * BM;
    const int j0  = tid << 1;            // column pair

    // init state to zero
    for (int e = tid; e < 128 * BM; e += 256) {
        ((float*)hs_s)[e] = 0.0f;
        ((float*)c_s)[e]  = 0.0f;
    }
    const float b0 = bh[j0];
    const float b1 = bh[j0 + 1];
    __syncthreads();

    for (int t = 0; t < T_; t++) {
        // ---- phase 1: z = xg_t + hs @ Wh + bh ----
        float acc[BM][2];
        #pragma unroll
        for (int r = 0; r < BM; r++) {
            float2 xv = *(const float2*)&g_xg[((size_t)(r0 + r) * T_ + t) * G4H + j0];
            acc[r][0] = b0 + xv.x;
            acc[r][1] = b1 + xv.y;
        }
        #pragma unroll 4
        for (int k = 0; k < H_; k++) {
            float2 w  = *(const float2*)&Wh[k * G4H + j0];
            float4 h0 = *(const float4*)&hs_s[k][0];
            float4 h1 = *(const float4*)&hs_s[k][4];
            acc[0][0] += h0.x * w.x;  acc[0][1] += h0.x * w.y;
            acc[1][0] += h0.y * w.x;  acc[1][1] += h0.y * w.y;
            acc[2][0] += h0.z * w.x;  acc[2][1] += h0.z * w.y;
            acc[3][0] += h0.w * w.x;  acc[3][1] += h0.w * w.y;
            acc[4][0] += h1.x * w.x;  acc[4][1] += h1.x * w.y;
            acc[5][0] += h1.y * w.x;  acc[5][1] += h1.y * w.y;
            acc[6][0] += h1.z * w.x;  acc[6][1] += h1.z * w.y;
            acc[7][0] += h1.w * w.x;  acc[7][1] += h1.w * w.y;
        }
        #pragma unroll
        for (int r = 0; r < BM; r++) {
            *(float2*)&z_s[r][j0] = make_float2(acc[r][0], acc[r][1]);
        }
        __syncthreads();

        // ---- phase 2: gates + state update ----
        #pragma unroll
        for (int q = 0; q < 4; q++) {
            int e  = tid + 256 * q;          // 0..1023
            int kk = e & 127;
            int r  = e >> 7;
            float zi = z_s[r][kk];
            float zf = z_s[r][128 + kk];
            float zg = z_s[r][256 + kk];
            float zo = z_s[r][384 + kk];
            float ig = 1.0f / (1.0f + __expf(-zi));
            float fg = 1.0f / (1.0f + __expf(-zf));
            float gg = tanhf(zg);
            float og = 1.0f / (1.0f + __expf(-zo));
            float c  = fg * c_s[r][kk] + ig * gg;
            c_s[r][kk]  = c;
            hs_s[kk][r] = og * tanhf(c);
        }
        __syncthreads();
    }

    // write final hidden state
    #pragma unroll
    for (int q = 0; q < 4; q++) {
        int e  = tid + 256 * q;
        int kk = e & 127;
        int r  = e >> 7;
        g_x[(r0 + r) * H_ + kk] = hs_s[kk][r];
    }
}

// ---------------------------------------------------------------------------
// Heads. Layer 1: [1024,128]@[128,256] for actor + critic, tanh.
// ---------------------------------------------------------------------------
__global__ void __launch_bounds__(256) k_head1(const float* __restrict__ Wa1,
                                               const float* __restrict__ ba1,
                                               const float* __restrict__ Wc1,
                                               const float* __restrict__ bc1) {
    __shared__ float xs[H_];
    const int row = blockIdx.x;
    const int j   = threadIdx.x;
    if (j < H_) xs[j] = g_x[row * H_ + j];
    __syncthreads();

    float sa = ba1[j];
    float sv = bc1[j];
    #pragma unroll 8
    for (int k = 0; k < H_; k++) {
        float x = xs[k];
        sa += x * Wa1[k * D_ + j];
        sv += x * Wc1[k * D_ + j];
    }
    g_a1[row * D_ + j] = tanhf(sa);
    g_v1[row * D_ + j] = tanhf(sv);
}

// Layer 2: [1024,256]@[256,256] for actor + critic, tanh.
__global__ void __launch_bounds__(256) k_head2(const float* __restrict__ Wa2,
                                               const float* __restrict__ ba2,
                                               const float* __restrict__ Wc2,
                                               const float* __restrict__ bc2) {
    __shared__ float as[D_];
    __shared__ float vs[D_];
    const int row = blockIdx.x;
    const int j   = threadIdx.x;
    as[j] = g_a1[row * D_ + j];
    vs[j] = g_v1[row * D_ + j];
    __syncthreads();

    float sa = ba2[j];
    float sv = bc2[j];
    #pragma unroll 8
    for (int k = 0; k < D_; k++) {
        sa += as[k] * Wa2[k * D_ + j];
        sv += vs[k] * Wc2[k * D_ + j];
    }
    g_a2[row * D_ + j] = tanhf(sa);
    g_v2[row * D_ + j] = tanhf(sv);
}

// Layer 3 + pack: out[row] = [mean(8), std(8), value(1)]
__global__ void __launch_bounds__(32) k_head3(const float* __restrict__ Wa3,
                                              const float* __restrict__ ba3,
                                              const float* __restrict__ Wc3,
                                              const float* __restrict__ bc3,
                                              const float* __restrict__ log_std,
                                              float* __restrict__ out) {
    const int row = blockIdx.x;
    const int t   = threadIdx.x;

    if (t < A_) {
        // policy mean, column t
        float s = ba3[t];
        #pragma unroll 8
        for (int k = 0; k < D_; k++)
            s += g_a2[row * D_ + k] * Wa3[k * A_ + t];
        out[row * (2 * A_ + 1) + t] = s;
    } else if (t < 2 * A_) {
        out[row * (2 * A_ + 1) + t] = expf(log_std[t - A_]);
    } else if (t == 2 * A_) {
        float s = bc3[0];
        #pragma unroll 8
        for (int k = 0; k < D_; k++)
            s += g_v2[row * D_ + k] * Wc3[k];
        out[row * (2 * A_ + 1) + 2 * A_] = s;
    }
}

// ---------------------------------------------------------------------------
extern "C" void kernel_launch(void* const* d_in, const int* in_sizes, int n_in,
                              void* d_out, int out_size) {
    const float* h       = (const float*)d_in[0];
    const float* Wx      = (const float*)d_in[1];
    const float* Wh      = (const float*)d_in[2];
    const float* bh      = (const float*)d_in[3];
    const float* Wa1     = (const float*)d_in[4];
    const float* ba1     = (const float*)d_in[5];
    const float* Wa2     = (const float*)d_in[6];
    const float* ba2     = (const float*)d_in[7];
    const float* Wa3     = (const float*)d_in[8];
    const float* ba3     = (const float*)d_in[9];
    const float* log_std = (const float*)d_in[10];
    const float* Wc1     = (const float*)d_in[11];
    const float* bc1     = (const float*)d_in[12];
    const float* Wc2     = (const float*)d_in[13];
    const float* bc2     = (const float*)d_in[14];
    const float* Wc3     = (const float*)d_in[15];
    const float* bc3     = (const float*)d_in[16];
    float* out = (float*)d_out;

    dim3 g1((B_ * T_) / 64, G4H / 64);          // (4096, 8)
    k_xg_gemm<<<g1, 256>>>(h, Wx);
    k_lstm<<<B_ / BM, 256>>>(Wh, bh);           // 128 CTAs
    k_head1<<<B_, 256>>>(Wa1, ba1, Wc1, bc1);
    k_head2<<<B_, 256>>>(Wa2, ba2, Wc2, bc2);
    k_head3<<<B_, 32>>>(Wa3, ba3, Wc3, bc3, log_std, out);
}

// round 4
// speedup vs baseline: 1.0011x; 1.0011x over previous
#include <cuda_runtime.h>
#include <math.h>

#define B_   1024
#define T_   256
#define F_   128
#define H_   128
#define G4H  512
#define D_   256
#define A_   8

// ---------------- scratch (device globals; no allocation allowed) ----------
__device__ float g_xg[(size_t)B_ * T_ * G4H];   // 512 MB: input projections [B*T, 4H]
__device__ float g_x [B_ * H_];                 // final hidden state
__device__ float g_a1[B_ * D_];
__device__ float g_v1[B_ * D_];
__device__ float g_a2[B_ * D_];
__device__ float g_v2[B_ * D_];

// ---------------------------------------------------------------------------
// K1: xg = h @ Wx   ([B*T,128] @ [128,512])
// 64x64 block tile, BK=64 (two K phases), 256 threads, 4x4 microtile.
// ---------------------------------------------------------------------------
__global__ void __launch_bounds__(256) k_xg_gemm(const float* __restrict__ h,
                                                 const float* __restrict__ Wx) {
    __shared__ float As[64][64];   // As[k][m]
    __shared__ float Bs[64][64];   // Bs[k][n]

    const int tid = threadIdx.x;
    const int m0  = blockIdx.x * 64;
    const int n0  = blockIdx.y * 64;
    const int ty  = tid >> 4;      // 0..15
    const int tx  = tid & 15;      // 0..15

    float acc[4][4] = {};

    #pragma unroll
    for (int k0 = 0; k0 < F_; k0 += 64) {
        // load A tile (transpose into As[k][m])
        #pragma unroll
        for (int t = 0; t < 4; t++) {
            int linear = tid + 256 * t;          // 0..1023
            int m  = linear >> 4;                // 0..63
            int kq = (linear & 15) << 2;         // 0,4,...,60
            float4 v = *(const float4*)&h[(size_t)(m0 + m) * F_ + k0 + kq];
            As[kq + 0][m] = v.x;
            As[kq + 1][m] = v.y;
            As[kq + 2][m] = v.z;
            As[kq + 3][m] = v.w;
        }
        // load B tile
        #pragma unroll
        for (int t = 0; t < 4; t++) {
            int linear = tid + 256 * t;
            int kb = linear >> 4;                // 0..63
            int n4 = (linear & 15) << 2;         // 0..60
            *(float4*)&Bs[kb][n4] =
                *(const float4*)&Wx[(size_t)(k0 + kb) * G4H + n0 + n4];
        }
        __syncthreads();

        #pragma unroll 8
        for (int k = 0; k < 64; k++) {
            float4 a4 = *(const float4*)&As[k][ty << 2];
            float4 b4 = *(const float4*)&Bs[k][tx << 2];
            float av[4] = {a4.x, a4.y, a4.z, a4.w};
            float bv[4] = {b4.x, b4.y, b4.z, b4.w};
            #pragma unroll
            for (int i = 0; i < 4; i++)
                #pragma unroll
                for (int j = 0; j < 4; j++)
                    acc[i][j] += av[i] * bv[j];
        }
        __syncthreads();
    }

    #pragma unroll
    for (int i = 0; i < 4; i++) {
        float4 v = make_float4(acc[i][0], acc[i][1], acc[i][2], acc[i][3]);
        *(float4*)&g_xg[(size_t)(m0 + (ty << 2) + i) * G4H + n0 + (tx << 2)] = v;
    }
}

// ---------------------------------------------------------------------------
// K2: fused LSTM scan. Each CTA owns BM=8 batch rows for all T=256 steps.
// 256 threads; thread j computes z columns (2j, 2j+1) for all 8 rows.
// Wh streamed from L2 each step (Wh is 256KB, resident in L2).
// ---------------------------------------------------------------------------
#define BM 8

__global__ void __launch_bounds__(256) k_lstm(const float* __restrict__ Wh,
                                              const float* __restrict__ bh) {
    __shared__ float hs_s[128][BM];      // transposed: hs_s[k][r]
    __shared__ float c_s[BM][128];
    __shared__ float z_s[BM][G4H];

    const int tid = threadIdx.x;
    const int r0  = blockIdx.x * BM;
    const int j0  = tid << 1;            // column pair

    // init state to zero
    for (int e = tid; e < 128 * BM; e += 256) {
        ((float*)hs_s)[e] = 0.0f;
        ((float*)c_s)[e]  = 0.0f;
    }
    const float b0 = bh[j0];
    const float b1 = bh[j0 + 1];
    __syncthreads();

    for (int t = 0; t < T_; t++) {
        // ---- phase 1: z = xg_t + hs @ Wh + bh ----
        float acc[BM][2];
        #pragma unroll
        for (int r = 0; r < BM; r++) {
            float2 xv = *(const float2*)&g_xg[((size_t)(r0 + r) * T_ + t) * G4H + j0];
            acc[r][0] = b0 + xv.x;
            acc[r][1] = b1 + xv.y;
        }
        #pragma unroll 4
        for (int k = 0; k < H_; k++) {
            float2 w  = *(const float2*)&Wh[k * G4H + j0];
            float4 h0 = *(const float4*)&hs_s[k][0];
            float4 h1 = *(const float4*)&hs_s[k][4];
            acc[0][0] += h0.x * w.x;  acc[0][1] += h0.x * w.y;
            acc[1][0] += h0.y * w.x;  acc[1][1] += h0.y * w.y;
            acc[2][0] += h0.z * w.x;  acc[2][1] += h0.z * w.y;
            acc[3][0] += h0.w * w.x;  acc[3][1] += h0.w * w.y;
            acc[4][0] += h1.x * w.x;  acc[4][1] += h1.x * w.y;
            acc[5][0] += h1.y * w.x;  acc[5][1] += h1.y * w.y;
            acc[6][0] += h1.z * w.x;  acc[6][1] += h1.z * w.y;
            acc[7][0] += h1.w * w.x;  acc[7][1] += h1.w * w.y;
        }
        #pragma unroll
        for (int r = 0; r < BM; r++) {
            *(float2*)&z_s[r][j0] = make_float2(acc[r][0], acc[r][1]);
        }
        __syncthreads();

        // ---- phase 2: gates + state update ----
        #pragma unroll
        for (int q = 0; q < 4; q++) {
            int e  = tid + 256 * q;          // 0..1023
            int kk = e & 127;
            int r  = e >> 7;
            float zi = z_s[r][kk];
            float zf = z_s[r][128 + kk];
            float zg = z_s[r][256 + kk];
            float zo = z_s[r][384 + kk];
            float ig = 1.0f / (1.0f + __expf(-zi));
            float fg = 1.0f / (1.0f + __expf(-zf));
            float gg = tanhf(zg);
            float og = 1.0f / (1.0f + __expf(-zo));
            float c  = fg * c_s[r][kk] + ig * gg;
            c_s[r][kk]  = c;
            hs_s[kk][r] = og * tanhf(c);
        }
        __syncthreads();
    }

    // write final hidden state
    #pragma unroll
    for (int q = 0; q < 4; q++) {
        int e  = tid + 256 * q;
        int kk = e & 127;
        int r  = e >> 7;
        g_x[(r0 + r) * H_ + kk] = hs_s[kk][r];
    }
}

// ---------------------------------------------------------------------------
// Heads. Layer 1: [1024,128]@[128,256] for actor + critic, tanh.
// ---------------------------------------------------------------------------
__global__ void __launch_bounds__(256) k_head1(const float* __restrict__ Wa1,
                                               const float* __restrict__ ba1,
                                               const float* __restrict__ Wc1,
                                               const float* __restrict__ bc1) {
    __shared__ float xs[H_];
    const int row = blockIdx.x;
    const int j   = threadIdx.x;
    if (j < H_) xs[j] = g_x[row * H_ + j];
    __syncthreads();

    float sa = ba1[j];
    float sv = bc1[j];
    #pragma unroll 8
    for (int k = 0; k < H_; k++) {
        float x = xs[k];
        sa += x * Wa1[k * D_ + j];
        sv += x * Wc1[k * D_ + j];
    }
    g_a1[row * D_ + j] = tanhf(sa);
    g_v1[row * D_ + j] = tanhf(sv);
}

// Layer 2: [1024,256]@[256,256] for actor + critic, tanh.
__global__ void __launch_bounds__(256) k_head2(const float* __restrict__ Wa2,
                                               const float* __restrict__ ba2,
                                               const float* __restrict__ Wc2,
                                               const float* __restrict__ bc2) {
    __shared__ float as[D_];
    __shared__ float vs[D_];
    const int row = blockIdx.x;
    const int j   = threadIdx.x;
    as[j] = g_a1[row * D_ + j];
    vs[j] = g_v1[row * D_ + j];
    __syncthreads();

    float sa = ba2[j];
    float sv = bc2[j];
    #pragma unroll 8
    for (int k = 0; k < D_; k++) {
        sa += as[k] * Wa2[k * D_ + j];
        sv += vs[k] * Wc2[k * D_ + j];
    }
    g_a2[row * D_ + j] = tanhf(sa);
    g_v2[row * D_ + j] = tanhf(sv);
}

// Layer 3 + pack: out[row] = [mean(8), std(8), value(1)]
__global__ void __launch_bounds__(32) k_head3(const float* __restrict__ Wa3,
                                              const float* __restrict__ ba3,
                                              const float* __restrict__ Wc3,
                                              const float* __restrict__ bc3,
                                              const float* __restrict__ log_std,
                                              float* __restrict__ out) {
    const int row = blockIdx.x;
    const int t   = threadIdx.x;

    if (t < A_) {
        // policy mean, column t
        float s = ba3[t];
        #pragma unroll 8
        for (int k = 0; k < D_; k++)
            s += g_a2[row * D_ + k] * Wa3[k * A_ + t];
        out[row * (2 * A_ + 1) + t] = s;
    } else if (t < 2 * A_) {
        out[row * (2 * A_ + 1) + t] = expf(log_std[t - A_]);
    } else if (t == 2 * A_) {
        float s = bc3[0];
        #pragma unroll 8
        for (int k = 0; k < D_; k++)
            s += g_v2[row * D_ + k] * Wc3[k];
        out[row * (2 * A_ + 1) + 2 * A_] = s;
    }
}

// ---------------------------------------------------------------------------
extern "C" void kernel_launch(void* const* d_in, const int* in_sizes, int n_in,
                              void* d_out, int out_size) {
    const float* h       = (const float*)d_in[0];
    const float* Wx      = (const float*)d_in[1];
    const float* Wh      = (const float*)d_in[2];
    const float* bh      = (const float*)d_in[3];
    const float* Wa1     = (const float*)d_in[4];
    const float* ba1     = (const float*)d_in[5];
    const float* Wa2     = (const float*)d_in[6];
    const float* ba2     = (const float*)d_in[7];
    const float* Wa3     = (const float*)d_in[8];
    const float* ba3     = (const float*)d_in[9];
    const float* log_std = (const float*)d_in[10];
    const float* Wc1     = (const float*)d_in[11];
    const float* bc1     = (const float*)d_in[12];
    const float* Wc2     = (const float*)d_in[13];
    const float* bc2     = (const float*)d_in[14];
    const float* Wc3     = (const float*)d_in[15];
    const float* bc3     = (const float*)d_in[16];
    float* out = (float*)d_out;

    dim3 g1((B_ * T_) / 64, G4H / 64);          // (4096, 8)
    k_xg_gemm<<<g1, 256>>>(h, Wx);
    k_lstm<<<B_ / BM, 256>>>(Wh, bh);           // 128 CTAs
    k_head1<<<B_, 256>>>(Wa1, ba1, Wc1, bc1);
    k_head2<<<B_, 256>>>(Wa2, ba2, Wc2, bc2);
    k_head3<<<B_, 32>>>(Wa3, ba3, Wc3, bc3, log_std, out);
}

// round 6
// speedup vs baseline: 1.3664x; 1.3649x over previous
#include <cuda_runtime.h>
#include <cuda_bf16.h>
#include <math.h>
#include <stdint.h>

#define B_ 1024
#define T_ 256
#define F_ 128
#define H_ 128
#define G4H 512
#define D_ 256
#define A_ 8
typedef unsigned long long u64;

__device__ float g_xg[(size_t)B_*T_*G4H];
__device__ float g_WhT[G4H*H_];
__device__ float g_x[B_*H_];
__device__ float g_a1[B_*D_]; __device__ float g_v1[B_*D_];
__device__ float g_a2[B_*D_]; __device__ float g_v2[B_*D_];

// ---------------- helpers ----------------
__device__ __forceinline__ uint32_t s2u(const void* p){
  uint32_t a; asm("{ .reg .u64 t; cvta.to.shared.u64 t, %1; cvt.u32.u64 %0, t; }":"=r"(a):"l"(p)); return a;
}
__device__ __forceinline__ u64 fma2(u64 a, u64 b, u64 c){
  u64 d; asm("fma.rn.f32x2 %0,%1,%2,%3;":"=l"(d):"l"(a),"l"(b),"l"(c)); return d;
}
__device__ __forceinline__ float2 up2(u64 v){ float2 f; asm("mov.b64 {%0,%1},%2;":"=f"(f.x),"=f"(f.y):"l"(v)); return f; }
__device__ __forceinline__ void ldsm4(uint32_t* r, uint32_t a){
  asm volatile("ldmatrix.sync.aligned.m8n8.x4.shared.b16 {%0,%1,%2,%3},[%4];"
    :"=r"(r[0]),"=r"(r[1]),"=r"(r[2]),"=r"(r[3]):"r"(a));
}
__device__ __forceinline__ void ldsm2t(uint32_t* r, uint32_t a){
  asm volatile("ldmatrix.sync.aligned.m8n8.x2.trans.shared.b16 {%0,%1},[%2];"
    :"=r"(r[0]),"=r"(r[1]):"r"(a));
}
__device__ __forceinline__ void mma16816(float* d, const uint32_t* a, const uint32_t* b){
  asm volatile("mma.sync.aligned.m16n8k16.row.col.f32.bf16.bf16.f32 "
    "{%0,%1,%2,%3},{%4,%5,%6,%7},{%8,%9},{%0,%1,%2,%3};"
    :"+f"(d[0]),"+f"(d[1]),"+f"(d[2]),"+f"(d[3])
    :"r"(a[0]),"r"(a[1]),"r"(a[2]),"r"(a[3]),"r"(b[0]),"r"(b[1]));
}
__device__ __forceinline__ void splitst(float4 v, __nv_bfloat16* Hs, __nv_bfloat16* Ls){
  __nv_bfloat16 h0=__float2bfloat16_rn(v.x),h1=__float2bfloat16_rn(v.y);
  __nv_bfloat16 h2=__float2bfloat16_rn(v.z),h3=__float2bfloat16_rn(v.w);
  *(__nv_bfloat162*)(Hs)  =__halves2bfloat162(h0,h1);
  *(__nv_bfloat162*)(Hs+2)=__halves2bfloat162(h2,h3);
  *(__nv_bfloat162*)(Ls)  =__halves2bfloat162(__float2bfloat16_rn(v.x-__bfloat162float(h0)),
                                              __float2bfloat16_rn(v.y-__bfloat162float(h1)));
  *(__nv_bfloat162*)(Ls+2)=__halves2bfloat162(__float2bfloat16_rn(v.z-__bfloat162float(h2)),
                                              __float2bfloat16_rn(v.w-__bfloat162float(h3)));
}

// ---------------- K1: xg = h @ Wx, bf16 hi/lo split mma ----------------
#define SA 136
__global__ void __launch_bounds__(256,1) k_xg_mma(const float* __restrict__ hin,
                                                  const float* __restrict__ Wx){
  extern __shared__ __align__(16) char smraw[];
  __nv_bfloat16 *Ah=(__nv_bfloat16*)smraw, *Al=Ah+128*SA, *Bh=Al+128*SA, *Bl=Bh+128*SA;
  const int tid=threadIdx.x, lane=tid&31, wid=tid>>5;
  const int m0=blockIdx.x*128, n0=blockIdx.y*128;

  #pragma unroll
  for(int i=0;i<16;i++){
    int idx=i*256+tid, row=idx>>5, c4=(idx&31)<<2;
    float4 a=*(const float4*)&hin[(size_t)(m0+row)*F_+c4];
    float4 b=*(const float4*)&Wx[(size_t)row*G4H+n0+c4];
    splitst(a, Ah+row*SA+c4, Al+row*SA+c4);
    splitst(b, Bh+row*SA+c4, Bl+row*SA+c4);
  }
  __syncthreads();

  const int wm=(wid>>2)*64, wn=(wid&3)*32;
  float acc[16][4];
  #pragma unroll
  for(int i=0;i<16;i++){acc[i][0]=0.f;acc[i][1]=0.f;acc[i][2]=0.f;acc[i][3]=0.f;}

  #pragma unroll
  for(int ks=0;ks<8;ks++){
    int k0=ks*16;
    uint32_t ah[4][4], al[4][4], bh[4][2], bl[4][2];
    int ar=lane&15, ac=k0+((lane>>4)<<3);
    #pragma unroll
    for(int mi=0;mi<4;mi++){
      ldsm4(ah[mi], s2u(Ah+(wm+mi*16+ar)*SA+ac));
      ldsm4(al[mi], s2u(Al+(wm+mi*16+ar)*SA+ac));
    }
    int br=k0+(lane&15);
    #pragma unroll
    for(int ni=0;ni<4;ni++){
      ldsm2t(bh[ni], s2u(Bh+br*SA+wn+ni*8));
      ldsm2t(bl[ni], s2u(Bl+br*SA+wn+ni*8));
    }
    #pragma unroll
    for(int mi=0;mi<4;mi++)
      #pragma unroll
      for(int ni=0;ni<4;ni++){
        float* d=acc[mi*4+ni];
        mma16816(d, ah[mi], bh[ni]);
        mma16816(d, ah[mi], bl[ni]);
        mma16816(d, al[mi], bh[ni]);
      }
  }
  int r=lane>>2, c2=(lane&3)*2;
  #pragma unroll
  for(int mi=0;mi<4;mi++)
    #pragma unroll
    for(int ni=0;ni<4;ni++){
      float* d=acc[mi*4+ni];
      size_t base=(size_t)(m0+wm+mi*16+r)*G4H + n0+wn+ni*8+c2;
      *(float2*)&g_xg[base]        =make_float2(d[0],d[1]);
      *(float2*)&g_xg[base+8*G4H]  =make_float2(d[2],d[3]);
    }
}

// ---------------- transpose Wh -> WhT[c][k] ----------------
__global__ void __launch_bounds__(256) k_wht(const float* __restrict__ Wh){
  int i=blockIdx.x*256+threadIdx.x;       // 65536
  int k=i>>9, c=i&511;
  g_WhT[c*H_+k]=Wh[i];
}

// ---------------- K2: fused LSTM, f32x2, Wh staged in smem ----------------
#define SWP 49
__global__ void __launch_bounds__(256,1) k_lstm(const float* __restrict__ bh){
  extern __shared__ __align__(16) char smraw[];
  float2* whs=(float2*)smraw;                 // [512][SWP], 48 kp used (k<96)
  float*  z  =(float*)smraw + 512*SWP*2;      // [8][512]
  float*  hsf= z + 8*512;                     // [64 kp][8 r][2] = 1024 floats
  float*  cs = hsf + 1024;                    // [8][128]
  u64* hsq=(u64*)hsf;
  const int tid=threadIdx.x;
  const int r0=blockIdx.x*8;
  const int c0=tid, c1=tid+256;

  for(int i=tid;i<512*48;i+=256){ int c=i/48, kp=i-c*48;
    whs[c*SWP+kp]=*(const float2*)&g_WhT[c*H_+2*kp]; }
  for(int i=tid;i<2048;i+=256) hsf[i]=0.f;    // hs + cs
  const float b0=bh[c0], b1=bh[c1];
  __syncthreads();

  for(int t=0;t<T_;t++){
    float xv0[8], xv1[8];
    #pragma unroll
    for(int r=0;r<8;r++){
      size_t o=((size_t)(r0+r)*T_+t)*G4H;
      xv0[r]=g_xg[o+c0]; xv1[r]=g_xg[o+c1];
    }
    u64 a0[8], a1[8];
    #pragma unroll
    for(int r=0;r<8;r++){a0[r]=0ull;a1[r]=0ull;}

    #pragma unroll 4
    for(int kp=0;kp<48;kp++){
      u64 w0=*(const u64*)&whs[c0*SWP+kp];
      u64 w1=*(const u64*)&whs[c1*SWP+kp];
      #pragma unroll
      for(int r=0;r<8;r++){ u64 h2=hsq[kp*8+r];
        a0[r]=fma2(h2,w0,a0[r]); a1[r]=fma2(h2,w1,a1[r]); }
    }
    #pragma unroll 4
    for(int kp=48;kp<64;kp++){
      u64 w0=*(const u64*)&g_WhT[c0*H_+2*kp];
      u64 w1=*(const u64*)&g_WhT[c1*H_+2*kp];
      #pragma unroll
      for(int r=0;r<8;r++){ u64 h2=hsq[kp*8+r];
        a0[r]=fma2(h2,w0,a0[r]); a1[r]=fma2(h2,w1,a1[r]); }
    }
    #pragma unroll
    for(int r=0;r<8;r++){
      float2 p=up2(a0[r]); z[r*G4H+c0]=p.x+p.y+xv0[r]+b0;
      float2 q=up2(a1[r]); z[r*G4H+c1]=q.x+q.y+xv1[r]+b1;
    }
    __syncthreads();
    #pragma unroll
    for(int qq=0;qq<4;qq++){
      int e=tid+256*qq, r=e>>7, u=e&127;
      const float* zr=z+r*G4H;
      float zi=zr[u], zf=zr[128+u], zg=zr[256+u], zo=zr[384+u];
      float ig=1.f/(1.f+__expf(-zi));
      float fg=1.f/(1.f+__expf(-zf));
      zg=fminf(fmaxf(zg,-15.f),15.f);
      float eg=__expf(-2.f*zg); float gg=(1.f-eg)/(1.f+eg);
      float og=1.f/(1.f+__expf(-zo));
      float cc=fg*cs[r*H_+u]+ig*gg; cs[r*H_+u]=cc;
      float cl=fminf(fmaxf(cc,-15.f),15.f);
      float ec=__expf(-2.f*cl); float th=(1.f-ec)/(1.f+ec);
      hsf[(u>>1)*16 + r*2 + (u&1)] = og*th;
    }
    __syncthreads();
  }
  #pragma unroll
  for(int qq=0;qq<4;qq++){
    int e=tid+256*qq, r=e>>7, u=e&127;
    g_x[(r0+r)*H_+u]=hsf[(u>>1)*16+r*2+(u&1)];
  }
}

// ---------------- heads (unchanged) ----------------
__global__ void __launch_bounds__(256) k_head1(const float* __restrict__ Wa1,const float* __restrict__ ba1,
                                               const float* __restrict__ Wc1,const float* __restrict__ bc1){
  __shared__ float xs[H_];
  const int row=blockIdx.x, j=threadIdx.x;
  if(j<H_) xs[j]=g_x[row*H_+j];
  __syncthreads();
  float sa=ba1[j], sv=bc1[j];
  #pragma unroll 8
  for(int k=0;k<H_;k++){ float x=xs[k]; sa+=x*Wa1[k*D_+j]; sv+=x*Wc1[k*D_+j]; }
  g_a1[row*D_+j]=tanhf(sa); g_v1[row*D_+j]=tanhf(sv);
}
__global__ void __launch_bounds__(256) k_head2(const float* __restrict__ Wa2,const float* __restrict__ ba2,
                                               const float* __restrict__ Wc2,const float* __restrict__ bc2){
  __shared__ float as[D_]; __shared__ float vs[D_];
  const int row=blockIdx.x, j=threadIdx.x;
  as[j]=g_a1[row*D_+j]; vs[j]=g_v1[row*D_+j];
  __syncthreads();
  float sa=ba2[j], sv=bc2[j];
  #pragma unroll 8
  for(int k=0;k<D_;k++){ sa+=as[k]*Wa2[k*D_+j]; sv+=vs[k]*Wc2[k*D_+j]; }
  g_a2[row*D_+j]=tanhf(sa); g_v2[row*D_+j]=tanhf(sv);
}
__global__ void __launch_bounds__(32) k_head3(const float* __restrict__ Wa3,const float* __restrict__ ba3,
                                              const float* __restrict__ Wc3,const float* __restrict__ bc3,
                                              const float* __restrict__ log_std, float* __restrict__ out){
  const int row=blockIdx.x, t=threadIdx.x;
  if(t<A_){
    float s=ba3[t];
    #pragma unroll 8
    for(int k=0;k<D_;k++) s+=g_a2[row*D_+k]*Wa3[k*A_+t];
    out[row*(2*A_+1)+t]=s;
  } else if(t<2*A_){
    out[row*(2*A_+1)+t]=expf(log_std[t-A_]);
  } else if(t==2*A_){
    float s=bc3[0];
    #pragma unroll 8
    for(int k=0;k<D_;k++) s+=g_v2[row*D_+k]*Wc3[k];
    out[row*(2*A_+1)+2*A_]=s;
  }
}

// ---------------------------------------------------------------------------
extern "C" void kernel_launch(void* const* d_in, const int* in_sizes, int n_in,
                              void* d_out, int out_size){
  const float* h       =(const float*)d_in[0];
  const float* Wx      =(const float*)d_in[1];
  const float* Wh      =(const float*)d_in[2];
  const float* bh      =(const float*)d_in[3];
  const float* Wa1     =(const float*)d_in[4];
  const float* ba1     =(const float*)d_in[5];
  const float* Wa2     =(const float*)d_in[6];
  const float* ba2     =(const float*)d_in[7];
  const float* Wa3     =(const float*)d_in[8];
  const float* ba3     =(const float*)d_in[9];
  const float* log_std =(const float*)d_in[10];
  const float* Wc1     =(const float*)d_in[11];
  const float* bc1     =(const float*)d_in[12];
  const float* Wc2     =(const float*)d_in[13];
  const float* bc2     =(const float*)d_in[14];
  const float* Wc3     =(const float*)d_in[15];
  const float* bc3     =(const float*)d_in[16];
  float* out=(float*)d_out;

  const int smK1 = 4*128*SA*2;                    // 139264 B
  const int smLS = 512*SWP*8 + 8*512*4 + 1024*4 + 1024*4;  // 225280 B
  cudaFuncSetAttribute(k_xg_mma, cudaFuncAttributeMaxDynamicSharedMemorySize, smK1);
  cudaFuncSetAttribute(k_lstm,   cudaFuncAttributeMaxDynamicSharedMemorySize, smLS);

  dim3 g1((B_*T_)/128, G4H/128);                  // (2048, 4)
  k_xg_mma<<<g1, 256, smK1>>>(h, Wx);
  k_wht<<<256, 256>>>(Wh);
  k_lstm<<<B_/8, 256, smLS>>>(bh);                // 128 CTAs
  k_head1<<<B_, 256>>>(Wa1, ba1, Wc1, bc1);
  k_head2<<<B_, 256>>>(Wa2, ba2, Wc2, bc2);
  k_head3<<<B_, 32>>>(Wa3, ba3, Wc3, bc3, log_std, out);
}

// round 7
// speedup vs baseline: 1.7874x; 1.3081x over previous
#include <cuda_runtime.h>
#include <cuda_bf16.h>
#include <math.h>
#include <stdint.h>

#define B_ 1024
#define T_ 256
#define F_ 128
#define H_ 128
#define G4H 512
#define D_ 256
#define A_ 8
typedef unsigned long long u64;

__device__ float g_xg[(size_t)B_*T_*G4H];
__device__ float g_x[B_*H_];
__device__ float g_a1[B_*D_]; __device__ float g_v1[B_*D_];
__device__ float g_a2[B_*D_]; __device__ float g_v2[B_*D_];

// ---------------- helpers ----------------
__device__ __forceinline__ uint32_t s2u(const void* p){
  uint32_t a; asm("{ .reg .u64 t; cvta.to.shared.u64 t, %1; cvt.u32.u64 %0, t; }":"=r"(a):"l"(p)); return a;
}
__device__ __forceinline__ u64 fma2(u64 a, u64 b, u64 c){
  u64 d; asm("fma.rn.f32x2 %0,%1,%2,%3;":"=l"(d):"l"(a),"l"(b),"l"(c)); return d;
}
__device__ __forceinline__ u64 pack2(float x, float y){
  u64 r; asm("mov.b64 %0,{%1,%2};":"=l"(r):"f"(x),"f"(y)); return r;
}
__device__ __forceinline__ float2 up2(u64 v){ float2 f; asm("mov.b64 {%0,%1},%2;":"=f"(f.x),"=f"(f.y):"l"(v)); return f; }
__device__ __forceinline__ void ldsm4(uint32_t* r, uint32_t a){
  asm volatile("ldmatrix.sync.aligned.m8n8.x4.shared.b16 {%0,%1,%2,%3},[%4];"
    :"=r"(r[0]),"=r"(r[1]),"=r"(r[2]),"=r"(r[3]):"r"(a));
}
__device__ __forceinline__ void ldsm2t(uint32_t* r, uint32_t a){
  asm volatile("ldmatrix.sync.aligned.m8n8.x2.trans.shared.b16 {%0,%1},[%2];"
    :"=r"(r[0]),"=r"(r[1]):"r"(a));
}
__device__ __forceinline__ void mma16816(float* d, const uint32_t* a, const uint32_t* b){
  asm volatile("mma.sync.aligned.m16n8k16.row.col.f32.bf16.bf16.f32 "
    "{%0,%1,%2,%3},{%4,%5,%6,%7},{%8,%9},{%0,%1,%2,%3};"
    :"+f"(d[0]),"+f"(d[1]),"+f"(d[2]),"+f"(d[3])
    :"r"(a[0]),"r"(a[1]),"r"(a[2]),"r"(a[3]),"r"(b[0]),"r"(b[1]));
}
__device__ __forceinline__ void splitst(float4 v, __nv_bfloat16* Hs, __nv_bfloat16* Ls){
  __nv_bfloat16 h0=__float2bfloat16_rn(v.x),h1=__float2bfloat16_rn(v.y);
  __nv_bfloat16 h2=__float2bfloat16_rn(v.z),h3=__float2bfloat16_rn(v.w);
  *(__nv_bfloat162*)(Hs)  =__halves2bfloat162(h0,h1);
  *(__nv_bfloat162*)(Hs+2)=__halves2bfloat162(h2,h3);
  *(__nv_bfloat162*)(Ls)  =__halves2bfloat162(__float2bfloat16_rn(v.x-__bfloat162float(h0)),
                                              __float2bfloat16_rn(v.y-__bfloat162float(h1)));
  *(__nv_bfloat162*)(Ls+2)=__halves2bfloat162(__float2bfloat16_rn(v.z-__bfloat162float(h2)),
                                              __float2bfloat16_rn(v.w-__bfloat162float(h3)));
}

// ---------------- K1: xg = h @ Wx, bf16 hi/lo split mma (unchanged) --------
#define SA 136
__global__ void __launch_bounds__(256,1) k_xg_mma(const float* __restrict__ hin,
                                                  const float* __restrict__ Wx){
  extern __shared__ __align__(16) char smraw[];
  __nv_bfloat16 *Ah=(__nv_bfloat16*)smraw, *Al=Ah+128*SA, *Bh=Al+128*SA, *Bl=Bh+128*SA;
  const int tid=threadIdx.x, lane=tid&31, wid=tid>>5;
  const int m0=blockIdx.x*128, n0=blockIdx.y*128;

  #pragma unroll
  for(int i=0;i<16;i++){
    int idx=i*256+tid, row=idx>>5, c4=(idx&31)<<2;
    float4 a=*(const float4*)&hin[(size_t)(m0+row)*F_+c4];
    float4 b=*(const float4*)&Wx[(size_t)row*G4H+n0+c4];
    splitst(a, Ah+row*SA+c4, Al+row*SA+c4);
    splitst(b, Bh+row*SA+c4, Bl+row*SA+c4);
  }
  __syncthreads();

  const int wm=(wid>>2)*64, wn=(wid&3)*32;
  float acc[16][4];
  #pragma unroll
  for(int i=0;i<16;i++){acc[i][0]=0.f;acc[i][1]=0.f;acc[i][2]=0.f;acc[i][3]=0.f;}

  #pragma unroll
  for(int ks=0;ks<8;ks++){
    int k0=ks*16;
    uint32_t ah[4][4], al[4][4], bh[4][2], bl[4][2];
    int ar=lane&15, ac=k0+((lane>>4)<<3);
    #pragma unroll
    for(int mi=0;mi<4;mi++){
      ldsm4(ah[mi], s2u(Ah+(wm+mi*16+ar)*SA+ac));
      ldsm4(al[mi], s2u(Al+(wm+mi*16+ar)*SA+ac));
    }
    int br=k0+(lane&15);
    #pragma unroll
    for(int ni=0;ni<4;ni++){
      ldsm2t(bh[ni], s2u(Bh+br*SA+wn+ni*8));
      ldsm2t(bl[ni], s2u(Bl+br*SA+wn+ni*8));
    }
    #pragma unroll
    for(int mi=0;mi<4;mi++)
      #pragma unroll
      for(int ni=0;ni<4;ni++){
        float* d=acc[mi*4+ni];
        mma16816(d, ah[mi], bh[ni]);
        mma16816(d, ah[mi], bl[ni]);
        mma16816(d, al[mi], bh[ni]);
      }
  }
  int r=lane>>2, c2=(lane&3)*2;
  #pragma unroll
  for(int mi=0;mi<4;mi++)
    #pragma unroll
    for(int ni=0;ni<4;ni++){
      float* d=acc[mi*4+ni];
      size_t base=(size_t)(m0+wm+mi*16+r)*G4H + n0+wn+ni*8+c2;
      *(float2*)&g_xg[base]        =make_float2(d[0],d[1]);
      *(float2*)&g_xg[base+8*G4H]  =make_float2(d[2],d[3]);
    }
}

// ---------------- K2: fused LSTM, 512 thr, 1 col/thr, f32x2 ----------------
#define KPS 48                   // k-pairs staged in smem (k < 96)
#define SWH 10                   // hsq row stride (u64) for conflict spread
__global__ void __launch_bounds__(512,1) k_lstm(const float* __restrict__ Wh,
                                                const float* __restrict__ bh){
  extern __shared__ __align__(16) char smraw[];
  u64*   whs=(u64*)smraw;                                  // [KPS][512]
  float* z  =(float*)(smraw + KPS*512*8);                  // [8][512]
  u64*   hsq=(u64*)((char*)z + 8*512*4);                   // [64][SWH] (8 used)
  float* cs =(float*)((char*)hsq + 64*SWH*8);              // [8][128]
  const int tid=threadIdx.x;
  const int r0 =blockIdx.x*8;
  const int c  =tid;

  // stage whs[kp][c] = (Wh[2kp][c], Wh[2kp+1][c]) — coalesced
  for(int kp=0;kp<KPS;kp++)
    whs[kp*512+c]=pack2(Wh[(size_t)(2*kp)*G4H+c], Wh[(size_t)(2*kp+1)*G4H+c]);
  // tail weights live in registers for all 256 steps
  u64 wt[16];
  #pragma unroll
  for(int i=0;i<16;i++){
    int kp=KPS+i;
    wt[i]=pack2(Wh[(size_t)(2*kp)*G4H+c], Wh[(size_t)(2*kp+1)*G4H+c]);
  }
  for(int i=tid;i<64*SWH;i+=512) hsq[i]=0ull;
  for(int i=tid;i<1024;i+=512) cs[i]=0.f;
  const float bb=bh[c];
  __syncthreads();

  for(int t=0;t<T_;t++){
    float xv[8];
    #pragma unroll
    for(int r=0;r<8;r++) xv[r]=g_xg[((size_t)(r0+r)*T_+t)*G4H + c];
    u64 a[8];
    #pragma unroll
    for(int r=0;r<8;r++) a[r]=0ull;

    #pragma unroll 2
    for(int kp=0;kp<KPS;kp++){
      u64 w=whs[kp*512+c];
      ulonglong2 h01=*(const ulonglong2*)&hsq[kp*SWH+0];
      ulonglong2 h23=*(const ulonglong2*)&hsq[kp*SWH+2];
      ulonglong2 h45=*(const ulonglong2*)&hsq[kp*SWH+4];
      ulonglong2 h67=*(const ulonglong2*)&hsq[kp*SWH+6];
      a[0]=fma2(h01.x,w,a[0]); a[1]=fma2(h01.y,w,a[1]);
      a[2]=fma2(h23.x,w,a[2]); a[3]=fma2(h23.y,w,a[3]);
      a[4]=fma2(h45.x,w,a[4]); a[5]=fma2(h45.y,w,a[5]);
      a[6]=fma2(h67.x,w,a[6]); a[7]=fma2(h67.y,w,a[7]);
    }
    #pragma unroll 2
    for(int i=0;i<16;i++){
      int kp=KPS+i;
      u64 w=wt[i];
      ulonglong2 h01=*(const ulonglong2*)&hsq[kp*SWH+0];
      ulonglong2 h23=*(const ulonglong2*)&hsq[kp*SWH+2];
      ulonglong2 h45=*(const ulonglong2*)&hsq[kp*SWH+4];
      ulonglong2 h67=*(const ulonglong2*)&hsq[kp*SWH+6];
      a[0]=fma2(h01.x,w,a[0]); a[1]=fma2(h01.y,w,a[1]);
      a[2]=fma2(h23.x,w,a[2]); a[3]=fma2(h23.y,w,a[3]);
      a[4]=fma2(h45.x,w,a[4]); a[5]=fma2(h45.y,w,a[5]);
      a[6]=fma2(h67.x,w,a[6]); a[7]=fma2(h67.y,w,a[7]);
    }
    #pragma unroll
    for(int r=0;r<8;r++){ float2 p=up2(a[r]); z[r*512+c]=p.x+p.y+xv[r]+bb; }
    __syncthreads();

    #pragma unroll
    for(int qq=0;qq<2;qq++){
      int e=tid+512*qq, r=e>>7, u=e&127;
      const float* zr=z+r*512;
      float zi=zr[u], zf=zr[128+u], zg=zr[256+u], zo=zr[384+u];
      float ig=1.f/(1.f+__expf(-zi));
      float fg=1.f/(1.f+__expf(-zf));
      zg=fminf(fmaxf(zg,-15.f),15.f);
      float eg=__expf(-2.f*zg); float gg=(1.f-eg)/(1.f+eg);
      float og=1.f/(1.f+__expf(-zo));
      float cc=fg*cs[r*H_+u]+ig*gg; cs[r*H_+u]=cc;
      float cl=fminf(fmaxf(cc,-15.f),15.f);
      float ec=__expf(-2.f*cl); float th=(1.f-ec)/(1.f+ec);
      ((float*)hsq)[(u>>1)*(2*SWH) + r*2 + (u&1)] = og*th;
    }
    __syncthreads();
  }
  #pragma unroll
  for(int qq=0;qq<2;qq++){
    int e=tid+512*qq, r=e>>7, u=e&127;
    g_x[(r0+r)*H_+u]=((float*)hsq)[(u>>1)*(2*SWH)+r*2+(u&1)];
  }
}

// ---------------- heads: 8 rows/CTA ----------------
__global__ void __launch_bounds__(512) k_head1(const float* __restrict__ Wa1,const float* __restrict__ ba1,
                                               const float* __restrict__ Wc1,const float* __restrict__ bc1){
  __shared__ float xs[8][H_];
  const int tid=threadIdx.x, half=tid>>8, j=tid&255, r0=blockIdx.x*8;
  for(int i=tid;i<8*H_;i+=512) xs[i>>7][i&127]=g_x[r0*H_+i];
  __syncthreads();
  const float* W = half? Wc1:Wa1;
  float acc[8];
  float b = half? bc1[j]:ba1[j];
  #pragma unroll
  for(int r=0;r<8;r++) acc[r]=b;
  #pragma unroll 4
  for(int k=0;k<H_;k++){
    float w=W[k*D_+j];
    #pragma unroll
    for(int r=0;r<8;r++) acc[r]+=xs[r][k]*w;
  }
  float* o = half? g_v1:g_a1;
  #pragma unroll
  for(int r=0;r<8;r++) o[(r0+r)*D_+j]=tanhf(acc[r]);
}
__global__ void __launch_bounds__(512) k_head2(const float* __restrict__ Wa2,const float* __restrict__ ba2,
                                               const float* __restrict__ Wc2,const float* __restrict__ bc2){
  __shared__ float s[2][8][D_];
  const int tid=threadIdx.x, half=tid>>8, j=tid&255, r0=blockIdx.x*8;
  for(int i=tid;i<8*D_;i+=512){
    int r=i>>8, cc=i&255;
    s[0][r][cc]=g_a1[(r0+r)*D_+cc];
    s[1][r][cc]=g_v1[(r0+r)*D_+cc];
  }
  __syncthreads();
  const float* W = half? Wc2:Wa2;
  float acc[8];
  float b = half? bc2[j]:ba2[j];
  #pragma unroll
  for(int r=0;r<8;r++) acc[r]=b;
  #pragma unroll 4
  for(int k=0;k<D_;k++){
    float w=W[k*D_+j];
    #pragma unroll
    for(int r=0;r<8;r++) acc[r]+=s[half][r][k]*w;
  }
  float* o = half? g_v2:g_a2;
  #pragma unroll
  for(int r=0;r<8;r++) o[(r0+r)*D_+j]=tanhf(acc[r]);
}
__global__ void __launch_bounds__(32) k_head3(const float* __restrict__ Wa3,const float* __restrict__ ba3,
                                              const float* __restrict__ Wc3,const float* __restrict__ bc3,
                                              const float* __restrict__ log_std, float* __restrict__ out){
  const int row=blockIdx.x, t=threadIdx.x;
  if(t<A_){
    float s=ba3[t];
    #pragma unroll 8
    for(int k=0;k<D_;k++) s+=g_a2[row*D_+k]*Wa3[k*A_+t];
    out[row*(2*A_+1)+t]=s;
  } else if(t<2*A_){
    out[row*(2*A_+1)+t]=expf(log_std[t-A_]);
  } else if(t==2*A_){
    float s=bc3[0];
    #pragma unroll 8
    for(int k=0;k<D_;k++) s+=g_v2[row*D_+k]*Wc3[k];
    out[row*(2*A_+1)+2*A_]=s;
  }
}

// ---------------------------------------------------------------------------
extern "C" void kernel_launch(void* const* d_in, const int* in_sizes, int n_in,
                              void* d_out, int out_size){
  const float* h       =(const float*)d_in[0];
  const float* Wx      =(const float*)d_in[1];
  const float* Wh      =(const float*)d_in[2];
  const float* bh      =(const float*)d_in[3];
  const float* Wa1     =(const float*)d_in[4];
  const float* ba1     =(const float*)d_in[5];
  const float* Wa2     =(const float*)d_in[6];
  const float* ba2     =(const float*)d_in[7];
  const float* Wa3     =(const float*)d_in[8];
  const float* ba3     =(const float*)d_in[9];
  const float* log_std =(const float*)d_in[10];
  const float* Wc1     =(const float*)d_in[11];
  const float* bc1     =(const float*)d_in[12];
  const float* Wc2     =(const float*)d_in[13];
  const float* bc2     =(const float*)d_in[14];
  const float* Wc3     =(const float*)d_in[15];
  const float* bc3     =(const float*)d_in[16];
  float* out=(float*)d_out;

  const int smK1 = 4*128*SA*2;                                   // 139264 B
  const int smLS = KPS*512*8 + 8*512*4 + 64*SWH*8 + 8*128*4;     // 222208 B
  cudaFuncSetAttribute(k_xg_mma, cudaFuncAttributeMaxDynamicSharedMemorySize, smK1);
  cudaFuncSetAttribute(k_lstm,   cudaFuncAttributeMaxDynamicSharedMemorySize, smLS);

  dim3 g1((B_*T_)/128, G4H/128);                  // (2048, 4)
  k_xg_mma<<<g1, 256, smK1>>>(h, Wx);
  k_lstm<<<B_/8, 512, smLS>>>(Wh, bh);            // 128 CTAs
  k_head1<<<B_/8, 512>>>(Wa1, ba1, Wc1, bc1);
  k_head2<<<B_/8, 512>>>(Wa2, ba2, Wc2, bc2);
  k_head3<<<B_, 32>>>(Wa3, ba3, Wc3, bc3, log_std, out);
}